// round 7
// baseline (speedup 1.0000x reference)
#include <cuda_runtime.h>

// out[b,t,d] = x[b,t,d] * (sum_{k<t} x[b,k,d])
// B=8, T=4096, D=1024, fp32. Single-pass: chunk data staged in SMEM,
// so DRAM traffic = 1 read + 1 write = 268 MB exactly.

#define T_DIM  4096
#define D_DIM  1024
#define LANES  8                 // d-lanes per block (32B = 1 sector)
#define SLICES 128               // t-slices per block
#define CHUNK  (T_DIM / SLICES)  // 32 t-steps per thread
#define SSUM_STRIDE (LANES + 1)

// SMEM word index for logical (t, lane), XOR-swizzled so that a warp
// (8 lanes x 4 consecutive slices, t values 32 apart) is bank-conflict-free.
__device__ __forceinline__ int sw_idx(int t, int lane) {
    return ((t ^ ((t >> 5) & 3)) << 3) + lane;
}

__global__ __launch_bounds__(LANES * SLICES, 1)
void siso_scan_mul_smem(const float* __restrict__ x, float* __restrict__ out,
                        int ngroups) {
    extern __shared__ float smem[];
    float* sdata = smem;                       // T_DIM * LANES words (swizzled)
    float* ssum  = smem + T_DIM * LANES;       // SLICES * SSUM_STRIDE words

    const int lane  = threadIdx.x & (LANES - 1);
    const int slice = threadIdx.x >> 3;        // 0..127, 4 consecutive per warp
    const int t0    = slice * CHUNK;

    const int d_tiles = D_DIM / LANES;         // 128

    for (int g = blockIdx.x; g < ngroups; g += gridDim.x) {
        const int b      = g >> 7;             // g / d_tiles
        const int d_tile = g & (d_tiles - 1);

        const unsigned base = (unsigned)b * (T_DIM * D_DIM)
                            + (unsigned)d_tile * LANES + (unsigned)lane;
        const float* __restrict__ p = x   + base + (unsigned)t0 * D_DIM;
        float*       __restrict__ q = out + base + (unsigned)t0 * D_DIM;

        // Phase 1: load chunk -> SMEM (swizzled), accumulate chunk sum.
        float s = 0.f;
        #pragma unroll
        for (int i = 0; i < CHUNK; ++i) {
            float v = p[(unsigned)i * D_DIM];
            sdata[sw_idx(t0 + i, lane)] = v;
            s += v;
        }
        ssum[slice * SSUM_STRIDE + lane] = s;
        __syncthreads();

        // Phase 2: exclusive prefix of the 128 chunk sums for this d-lane.
        // (lanes 0-7 at iteration j read 8 consecutive words; slices broadcast)
        float run = 0.f;
        for (int j = 0; j < slice; ++j) {
            run += ssum[j * SSUM_STRIDE + lane];
        }

        // Phase 3: read chunk back from SMEM, multiply by running prefix, store.
        #pragma unroll
        for (int i = 0; i < CHUNK; ++i) {
            float v = sdata[sw_idx(t0 + i, lane)];
            q[(unsigned)i * D_DIM] = v * run;
            run += v;
        }
        __syncthreads();   // protect sdata before next group's phase 1
    }
}

extern "C" void kernel_launch(void* const* d_in, const int* in_sizes, int n_in,
                              void* d_out, int out_size) {
    const float* x = (const float*)d_in[0];
    float* out = (float*)d_out;

    const int n = in_sizes[0];                     // B*T*D
    const int B = n / (T_DIM * D_DIM);             // 8
    const int ngroups = B * (D_DIM / LANES);       // 1024

    const int smem_bytes = (T_DIM * LANES + SLICES * SSUM_STRIDE) * (int)sizeof(float);

    static int configured = -1;
    int dev = 0, sms = 148;
    cudaGetDevice(&dev);
    cudaDeviceGetAttribute(&sms, cudaDevAttrMultiProcessorCount, dev);
    (void)configured;
    cudaFuncSetAttribute(siso_scan_mul_smem,
                         cudaFuncAttributeMaxDynamicSharedMemorySize, smem_bytes);

    int blocks = sms < ngroups ? sms : ngroups;    // persistent: one CTA per SM
    siso_scan_mul_smem<<<blocks, LANES * SLICES, smem_bytes>>>(x, out, ngroups);
}

// round 9
// speedup vs baseline: 1.1730x; 1.1730x over previous
#include <cuda_runtime.h>

// out[b,t,d] = x[b,t,d] * (sum_{k<t} x[b,k,d])
// B=8, T=4096, D=1024, fp32.
// Single-pass, register-staged: each thread keeps its 16-element t-chunk in
// registers, so DRAM traffic = 1 read + 1 write = 268 MB exactly.
// Block = 32 d-lanes x 32 slices, processes one (b, 32-wide d-tile) in 8
// sequential 512-step t-stages, carrying the prefix in smem.

#define T_DIM   4096
#define D_DIM   1024
#define D_TILE  32
#define SLICES  32
#define CHUNK   16                       // t-steps per thread per stage
#define STAGE_T (SLICES * CHUNK)         // 512
#define NSTAGE  (T_DIM / STAGE_T)        // 8

__global__ __launch_bounds__(D_TILE * SLICES, 1)
void siso_scan_reg(const float* __restrict__ x, float* __restrict__ out) {
    __shared__ float ssum[SLICES][D_TILE + 1];  // [slice][d], pad -> stride 33
    __shared__ float carry[D_TILE];             // running prefix per d-lane

    const int tid    = threadIdx.x;
    const int lane_d = tid & (D_TILE - 1);      // d within tile
    const int slice  = tid >> 5;                // t-slice 0..31
    const int wid    = tid >> 5;                // warp id == slice
    const int lid    = tid & 31;                // lane within warp == lane_d

    const int d_tiles = D_DIM / D_TILE;         // 32
    const int d_tile  = blockIdx.x & (d_tiles - 1);
    const int b       = blockIdx.x / d_tiles;

    const unsigned base = (unsigned)b * (T_DIM * D_DIM)
                        + (unsigned)d_tile * D_TILE + (unsigned)lane_d;

    if (tid < D_TILE) carry[tid] = 0.f;
    __syncthreads();

    for (int st = 0; st < NSTAGE; ++st) {
        const unsigned t_base = (unsigned)st * STAGE_T + (unsigned)slice * CHUNK;
        const float* __restrict__ p = x   + base + t_base * D_DIM;
        float*       __restrict__ q = out + base + t_base * D_DIM;

        // Load chunk into registers (16 independent LDGs -> deep MLP),
        // accumulate chunk sum.
        float v[CHUNK];
        float s = 0.f;
        #pragma unroll
        for (int i = 0; i < CHUNK; ++i) {
            v[i] = p[(unsigned)i * D_DIM];
            s += v[i];
        }
        ssum[slice][lane_d] = s;
        __syncthreads();

        // Warp-shuffle exclusive scan: warp `wid` scans d-lane `wid`'s 32
        // slice sums (lid indexes slice). Stride-33 smem -> conflict-free.
        {
            float val  = ssum[lid][wid];
            float incl = val;
            #pragma unroll
            for (int off = 1; off < 32; off <<= 1) {
                float n = __shfl_up_sync(0xFFFFFFFFu, incl, off);
                if (lid >= off) incl += n;
            }
            float c = carry[wid];
            ssum[lid][wid] = (incl - val) + c;    // exclusive prefix + carry-in
            if (lid == 31) carry[wid] = incl + c; // carry-out for next stage
        }
        __syncthreads();

        // Emit outputs from registers; stores drain while next stage's loads
        // can already issue (no barrier between this loop and the next load).
        float run = ssum[slice][lane_d];
        #pragma unroll
        for (int i = 0; i < CHUNK; ++i) {
            q[(unsigned)i * D_DIM] = v[i] * run;
            run += v[i];
        }
        // ssum/carry for the next stage are rewritten only after the next
        // __syncthreads() inside the loop (post-load), so no barrier needed
        // here for ssum reads: every thread has consumed its `run` already.
    }
}

extern "C" void kernel_launch(void* const* d_in, const int* in_sizes, int n_in,
                              void* d_out, int out_size) {
    const float* x = (const float*)d_in[0];
    float* out = (float*)d_out;

    const int n = in_sizes[0];                    // B*T*D
    const int B = n / (T_DIM * D_DIM);            // 8
    const int blocks = B * (D_DIM / D_TILE);      // 256

    siso_scan_reg<<<blocks, D_TILE * SLICES>>>(x, out);
}

// round 10
// speedup vs baseline: 1.4548x; 1.2402x over previous
#include <cuda_runtime.h>

// out[b,t,d] = x[b,t,d] * (sum_{k<t} x[b,k,d])
// B=8, T=4096, D=1024, fp32.
// Single-pass, register-staged, 4 CTAs/SM so independent CTAs' load and
// scan/emit phases overlap. DRAM traffic = 1 read + 1 write = 268 MB.

#define T_DIM   4096
#define D_DIM   1024
#define D_TILE  16
#define SLICES  16
#define CHUNK   16                       // t-steps per thread per stage
#define STAGE_T (SLICES * CHUNK)         // 256
#define NSTAGE  (T_DIM / STAGE_T)        // 16
#define NTHREADS (D_TILE * SLICES)       // 256

__global__ __launch_bounds__(NTHREADS, 4)
void siso_scan_reg4(const float* __restrict__ x, float* __restrict__ out) {
    __shared__ float ssum[SLICES][D_TILE + 1];  // [slice][d], stride 17
    __shared__ float carry[D_TILE];             // running prefix per d-lane

    const int tid    = threadIdx.x;
    const int lane_d = tid & (D_TILE - 1);      // d within tile (0..15)
    const int slice  = tid >> 4;                // t-slice (0..15)
    const int wid    = tid >> 5;                // warp id (0..7)
    const int lid    = tid & 31;

    const int d_tiles = D_DIM / D_TILE;         // 64
    const int d_tile  = blockIdx.x & (d_tiles - 1);
    const int b       = blockIdx.x >> 6;        // blockIdx.x / 64

    const unsigned base = (unsigned)b * (T_DIM * D_DIM)
                        + (unsigned)d_tile * D_TILE + (unsigned)lane_d;

    if (tid < D_TILE) carry[tid] = 0.f;
    __syncthreads();

    for (int st = 0; st < NSTAGE; ++st) {
        const unsigned t_base = (unsigned)st * STAGE_T + (unsigned)slice * CHUNK;
        const float* __restrict__ p = x   + base + t_base * D_DIM;
        float*       __restrict__ q = out + base + t_base * D_DIM;

        // Load chunk into registers (16 independent LDGs), chunk sum.
        float v[CHUNK];
        float s = 0.f;
        #pragma unroll
        for (int i = 0; i < CHUNK; ++i) {
            v[i] = p[(unsigned)i * D_DIM];
            s += v[i];
        }
        ssum[slice][lane_d] = s;
        __syncthreads();

        // Segmented shuffle scan: each warp scans two d-columns' 16 slice
        // sums (16-lane segments). stride-17 smem -> conflict-free.
        {
            const int d0    = (wid << 1) + (lid >> 4);   // d-column for this lane
            const int s_idx = lid & 15;                  // slice index in column
            float val  = ssum[s_idx][d0];
            float incl = val;
            #pragma unroll
            for (int off = 1; off < 16; off <<= 1) {
                float n = __shfl_up_sync(0xFFFFFFFFu, incl, off);
                if (s_idx >= off) incl += n;
            }
            float c = carry[d0];
            ssum[s_idx][d0] = (incl - val) + c;          // exclusive + carry-in
            if (s_idx == 15) carry[d0] = incl + c;       // carry-out
        }
        __syncthreads();

        // Emit from registers; next stage's loads can issue while stores drain.
        float run = ssum[slice][lane_d];
        #pragma unroll
        for (int i = 0; i < CHUNK; ++i) {
            q[(unsigned)i * D_DIM] = v[i] * run;
            run += v[i];
        }
        // ssum/carry are only rewritten after the next in-loop __syncthreads().
    }
}

extern "C" void kernel_launch(void* const* d_in, const int* in_sizes, int n_in,
                              void* d_out, int out_size) {
    const float* x = (const float*)d_in[0];
    float* out = (float*)d_out;

    const int n = in_sizes[0];                    // B*T*D
    const int B = n / (T_DIM * D_DIM);            // 8
    const int blocks = B * (D_DIM / D_TILE);      // 512

    siso_scan_reg4<<<blocks, NTHREADS>>>(x, out);
}